// round 13
// baseline (speedup 1.0000x reference)
#include <cuda_runtime.h>
#include <cstdint>

#define NN   1024
#define XD   128
#define HID  256
#define HP   128   // h-pairs

typedef unsigned long long u64;

// ---------------- scratch (device globals; no allocations) ----------------
__device__ float g_hxbT[HP * NN * 2];   // hx + b1, transposed, pair-interleaved [hp][n]{2}
__device__ float g_hyT [HP * NN * 2];   // hy, same layout
__device__ float g_c[NN];               // c_i = sum_h hy[i,h]*w2[h]
__device__ float g_d[NN];               // d_j = sum_h (hx[j,h]+b1[h])*w2[h]
__device__ float g_part[NN * 32];       // per (i, j-block) sum of exp(logit)
__device__ float g_diag[NN];            // T0_i = softplus(logit_ii)
__device__ int   g_ctr;

// ---------------- helpers ----------------
__device__ __forceinline__ void fadd2(float& r0, float& r1,
                                      float a0, float a1, float b0, float b1) {
    asm("{\n\t"
        ".reg .b64 ra, rb, rc;\n\t"
        "mov.b64 ra, {%2, %3};\n\t"
        "mov.b64 rb, {%4, %5};\n\t"
        "add.rn.f32x2 rc, ra, rb;\n\t"
        "mov.b64 {%0, %1}, rc;\n\t"
        "}" : "=f"(r0), "=f"(r1) : "f"(a0), "f"(a1), "f"(b0), "f"(b1));
}

__device__ __forceinline__ void cpa8(uint32_t dst, const void* src) {
    asm volatile("cp.async.ca.shared.global [%0], [%1], 8;\n"
                 :: "r"(dst), "l"(src));
}
__device__ __forceinline__ void cpa_commit() {
    asm volatile("cp.async.commit_group;\n" ::: "memory");
}
__device__ __forceinline__ void cpa_wait0() {
    asm volatile("cp.async.wait_group 0;\n" ::: "memory");
}

// ---------------- Kernel 0: profiling-shift no-op ----------------
__global__ void dummy_shift_kernel() {}

// ---------------- Kernel 1: h-projections ----------------
// z=0: g_hxbT = x@Wx + b1 ; z=1: g_hyT = y@Wy
// Tile 16n x 32h, 128 threads (2n x 2h per thread). Grid (64,8,2) = 1024
// blocks -> ~28 warps/SM (fixes grid starvation). A: coalesced LDG.128 +
// one-time smem transpose. W: smem chunks of 64 k (coalesced fill).
__global__ __launch_bounds__(128) void gemm_h(const float* __restrict__ X,
                                              const float* __restrict__ Y,
                                              const float* __restrict__ W1,
                                              const float* __restrict__ b1) {
    const int z = blockIdx.z;
    const float* A = (z == 0) ? X : Y;
    const float* W = W1 + z * XD * HID;
    float* outT    = (z == 0) ? g_hxbT : g_hyT;

    __shared__ float s_aT[XD][18];   // [k][n], 16 n used, pitch 18 (even)
    __shared__ float s_w[64][32];    // [k-chunk][h]

    const int tid = threadIdx.x;
    const int gn0 = blockIdx.x * 16;
    const int gh0 = blockIdx.y * 32;

    // Coalesced A load (16 rows x 32 float4) + transpose into s_aT
    #pragma unroll
    for (int r = 0; r < 4; r++) {
        int idx = tid + r * 128;
        int k4 = idx & 31, n_l = idx >> 5;       // n_l 0..15
        float4 v = *(const float4*)(A + (gn0 + n_l) * XD + 4 * k4);
        s_aT[4 * k4 + 0][n_l] = v.x;
        s_aT[4 * k4 + 1][n_l] = v.y;
        s_aT[4 * k4 + 2][n_l] = v.z;
        s_aT[4 * k4 + 3][n_l] = v.w;
    }

    const int tx = tid & 7;         // 8 n-threads, 2 n each
    const int ty = tid >> 3;        // 16 h-threads, 2 h each

    float acc[2][2];
    acc[0][0] = acc[0][1] = acc[1][0] = acc[1][1] = 0.0f;

    for (int kc = 0; kc < XD; kc += 64) {
        if (kc) __syncthreads();
        #pragma unroll
        for (int r = 0; r < 4; r++) {
            int idx = tid + r * 128;
            int h4 = idx & 7, k_l = idx >> 3;
            *(float4*)&s_w[k_l][4 * h4] =
                *(const float4*)(W + (kc + k_l) * HID + gh0 + 4 * h4);
        }
        __syncthreads();
        #pragma unroll 8
        for (int k = 0; k < 64; k++) {
            float2 a2 = *(const float2*)&s_aT[kc + k][2 * tx];
            float2 w2 = *(const float2*)&s_w[k][2 * ty];
            acc[0][0] = fmaf(w2.x, a2.x, acc[0][0]);
            acc[0][1] = fmaf(w2.x, a2.y, acc[0][1]);
            acc[1][0] = fmaf(w2.y, a2.x, acc[1][0]);
            acc[1][1] = fmaf(w2.y, a2.y, acc[1][1]);
        }
    }

    // write pair-interleaved transposed output (+b1 for z==0)
    {
        int h = gh0 + 2 * ty;                    // even
        float bb0 = 0.0f, bb1 = 0.0f;
        if (z == 0) { bb0 = b1[h]; bb1 = b1[h + 1]; }
        #pragma unroll
        for (int nn = 0; nn < 2; nn++) {
            int n = gn0 + 2 * tx + nn;
            *(float2*)&outT[((h >> 1) * NN + n) * 2] =
                make_float2(acc[0][nn] + bb0, acc[1][nn] + bb1);
        }
    }
}

// ---------------- Kernel 2: c_i, d_j rank-1 terms (unchanged) -------------
__global__ __launch_bounds__(256) void cd_kernel(const float* __restrict__ W2) {
    __shared__ float sc[256], sd[256];
    const int tid = threadIdx.x;
    const int i = blockIdx.x * 128 + (tid & 127);
    const int half = tid >> 7;
    const float2* hy = (const float2*)g_hyT;
    const float2* hx = (const float2*)g_hxbT;
    const float2* w2 = (const float2*)W2;
    float c = 0.0f, d = 0.0f;
    const int hp0 = half * 64;
    #pragma unroll 8
    for (int hp = hp0; hp < hp0 + 64; hp++) {
        float2 w = w2[hp];
        float2 a = hy[hp * NN + i];
        float2 b = hx[hp * NN + i];
        c = fmaf(a.x, w.x, fmaf(a.y, w.y, c));
        d = fmaf(b.x, w.x, fmaf(b.y, w.y, d));
    }
    sc[tid] = c; sd[tid] = d;
    __syncthreads();
    if (tid < 128) {
        g_c[i] = sc[tid] + sc[tid + 128];
        g_d[i] = sd[tid] + sd[tid + 128];
    }
}

// ---------------- Kernel 3: N^2 pair kernel + fused final reduction -------
// logit[i,j] = 0.5*(sum_h |hy[i,h]+hxb[j,h]|*w2[h] + c_i + d_j) + b2
// lse_i = log(1024 + sum_j e^logit)
// Tile 16i x 32j, 128 thr (4 warps x 4 i-rows; lane -> 1 j). Scalar inner
// (fadd2 + FFMA|z|), cp.async double-buffered 8-hp chunks, pitch 20
// (conflict-free LDS.128). Grid 2048 blocks -> ~40 resident warps/SM.
__global__ __launch_bounds__(128, 10) void pair_kernel(const float* __restrict__ W2,
                                                       const float* __restrict__ b2,
                                                       float* __restrict__ out) {
    __shared__ float s_a[2][16][20];   // [buf][i][h-chunk 16]
    __shared__ float s_b[2][32][20];   // [buf][j][h-chunk 16]
    __shared__ float s_w[HID];
    __shared__ bool  s_last;
    __shared__ float s_red[8];

    const int tid  = threadIdx.x;
    const int lane = tid & 31, w = tid >> 5;   // 4 warps; warp -> 4 i rows
    const int i0 = blockIdx.y * 16;
    const int j0 = blockIdx.x * 32;
    const u64* hyp = (const u64*)g_hyT;
    const u64* hxp = (const u64*)g_hxbT;

    // per-thread fill coordinates (fixed across chunks)
    const int a_i = tid & 15, a_hp = tid >> 4;     // hp 0..7, 1 cpa8
    const int b_j = tid & 31, b_hp = tid >> 5;     // r<2: hp = b_hp + 4r

    uint32_t sa_base = (uint32_t)__cvta_generic_to_shared(&s_a[0][0][0]);
    uint32_t sb_base = (uint32_t)__cvta_generic_to_shared(&s_b[0][0][0]);
    const uint32_t SA_BUF = 16 * 20 * 4;
    const uint32_t SB_BUF = 32 * 20 * 4;

    s_w[tid]       = W2[tid];
    s_w[tid + 128] = W2[tid + 128];

    float acc[4];
    #pragma unroll
    for (int a = 0; a < 4; a++) acc[a] = 0.0f;

    // ---- async fill of chunk `ch` (8 hp = 16 h) into buffer `b` ----
    auto fill = [&](int ch, int b) {
        const int hp0 = ch * 8;
        uint32_t sa = sa_base + b * SA_BUF;
        uint32_t sb = sb_base + b * SB_BUF;
        cpa8(sa + (a_i * 20 + 2 * a_hp) * 4,
             &hyp[(hp0 + a_hp) * NN + i0 + a_i]);
        #pragma unroll
        for (int r = 0; r < 2; r++) {
            int hp_l = b_hp + 4 * r;
            cpa8(sb + (b_j * 20 + 2 * hp_l) * 4,
                 &hxp[(hp0 + hp_l) * NN + j0 + b_j]);
        }
        cpa_commit();
    };

    fill(0, 0);
    cpa_wait0();
    __syncthreads();                           // also covers s_w

    int p = 0;
    for (int ch = 0; ch < 16; ch++) {          // 16 h (8 hp) per chunk
        if (ch < 15) fill(ch + 1, p ^ 1);

        #pragma unroll
        for (int st = 0; st < 4; st++) {       // 4 h per step
            float4 wv = *(const float4*)&s_w[ch * 16 + st * 4];
            float4 bj = *(const float4*)&s_b[p][lane][st * 4];
            #pragma unroll
            for (int ii = 0; ii < 4; ii++) {
                float4 av = *(const float4*)&s_a[p][w * 4 + ii][st * 4];
                float z0, z1;
                fadd2(z0, z1, av.x, av.y, bj.x, bj.y);
                acc[ii] = fmaf(fabsf(z0), wv.x, acc[ii]);
                acc[ii] = fmaf(fabsf(z1), wv.y, acc[ii]);
                fadd2(z0, z1, av.z, av.w, bj.z, bj.w);
                acc[ii] = fmaf(fabsf(z0), wv.z, acc[ii]);
                acc[ii] = fmaf(fabsf(z1), wv.w, acc[ii]);
            }
        }

        if (ch < 15) {
            cpa_wait0();
            __syncthreads();
            p ^= 1;
        }
    }

    // ---- epilogue: per-i sum of exp over this block's 32 j's ----
    const float b2v = b2[0];
    const int gj = j0 + lane;
    const float dv = g_d[gj];
    #pragma unroll
    for (int ii = 0; ii < 4; ii++) {
        const int gi = i0 + w * 4 + ii;
        float logit = 0.5f * (acc[ii] + g_c[gi] + dv) + b2v;
        float e = __expf(logit);
        if (gi == gj)
            g_diag[gi] = fmaxf(logit, 0.0f) + log1pf(__expf(-fabsf(logit)));
        e += __shfl_xor_sync(0xFFFFFFFFu, e, 16);
        e += __shfl_xor_sync(0xFFFFFFFFu, e, 8);
        e += __shfl_xor_sync(0xFFFFFFFFu, e, 4);
        e += __shfl_xor_sync(0xFFFFFFFFu, e, 2);
        e += __shfl_xor_sync(0xFFFFFFFFu, e, 1);
        if (lane == 0) g_part[gi * 32 + blockIdx.x] = e;
    }

    // ---- last block does the final reduction ----
    __threadfence();
    __syncthreads();
    if (tid == 0) {
        int old = atomicAdd(&g_ctr, 1);
        s_last = (old == 32 * 64 - 1);
    }
    __syncthreads();
    if (!s_last) return;
    __threadfence();

    float sumT0 = 0.0f, sumL = 0.0f;
    #pragma unroll
    for (int r = 0; r < 8; r++) {
        int i = tid * 8 + r;
        const float4* pp = (const float4*)&g_part[i * 32];
        float s = 0.0f;
        #pragma unroll
        for (int q = 0; q < 8; q++) {
            float4 f = pp[q];
            s += (f.x + f.y) + (f.z + f.w);
        }
        sumL  += __logf(1024.0f + s);
        sumT0 += g_diag[i];
    }
    #pragma unroll
    for (int dlt = 16; dlt >= 1; dlt >>= 1) {
        sumT0 += __shfl_xor_sync(0xFFFFFFFFu, sumT0, dlt);
        sumL  += __shfl_xor_sync(0xFFFFFFFFu, sumL,  dlt);
    }
    if (lane == 0) { s_red[w] = sumT0; s_red[4 + w] = sumL; }
    __syncthreads();
    if (tid == 0) {
        float t0 = (s_red[0] + s_red[1]) + (s_red[2] + s_red[3]);
        float l  = (s_red[4] + s_red[5]) + (s_red[6] + s_red[7]);
        const float invn = 1.0f / 1024.0f;
        out[0] = t0 * invn - (l * invn - logf(1024.0f));
        g_ctr = 0;
    }
}

// ---------------- launch ----------------
extern "C" void kernel_launch(void* const* d_in, const int* in_sizes, int n_in,
                              void* d_out, int out_size) {
    (void)in_sizes; (void)n_in; (void)out_size;
    const float* X  = (const float*)d_in[0];
    const float* Y  = (const float*)d_in[1];
    const float* W1 = (const float*)d_in[2];
    const float* b1 = (const float*)d_in[3];
    const float* W2 = (const float*)d_in[4];
    const float* b2 = (const float*)d_in[5];

    dummy_shift_kernel<<<1, 32>>>();
    gemm_h   <<<dim3(64, 8, 2), 128>>>(X, Y, W1, b1);
    cd_kernel<<<8, 256>>>(W2);
    pair_kernel<<<dim3(32, 64), 128>>>(W2, b2, (float*)d_out);
}

// round 15
// speedup vs baseline: 1.2219x; 1.2219x over previous
#include <cuda_runtime.h>
#include <cstdint>

#define NN   1024
#define XD   128
#define HID  256
#define HP   128   // h-pairs

typedef unsigned long long u64;

// ---------------- scratch (device globals; no allocations) ----------------
__device__ float g_hxbT[HP * NN * 2];   // hx + b1, transposed, pair-interleaved [hp][n]{2}
__device__ float g_hyT [HP * NN * 2];   // hy, same layout
__device__ float g_c[NN];               // c_i = sum_h hy[i,h]*w2[h]
__device__ float g_d[NN];               // d_j = sum_h (hx[j,h]+b1[h])*w2[h]
__device__ float g_part[NN * 16];       // per (i, j-block) sum of exp(logit)
__device__ float g_diag[NN];            // T0_i = softplus(logit_ii)
__device__ int   g_ctr;

// ---------------- helpers ----------------
__device__ __forceinline__ void fadd2(float& r0, float& r1,
                                      float a0, float a1, float b0, float b1) {
    asm("{\n\t"
        ".reg .b64 ra, rb, rc;\n\t"
        "mov.b64 ra, {%2, %3};\n\t"
        "mov.b64 rb, {%4, %5};\n\t"
        "add.rn.f32x2 rc, ra, rb;\n\t"
        "mov.b64 {%0, %1}, rc;\n\t"
        "}" : "=f"(r0), "=f"(r1) : "f"(a0), "f"(a1), "f"(b0), "f"(b1));
}

__device__ __forceinline__ void cpa8(uint32_t dst, const void* src) {
    asm volatile("cp.async.ca.shared.global [%0], [%1], 8;\n"
                 :: "r"(dst), "l"(src));
}
__device__ __forceinline__ void cpa_commit() {
    asm volatile("cp.async.commit_group;\n" ::: "memory");
}
__device__ __forceinline__ void cpa_wait0() {
    asm volatile("cp.async.wait_group 0;\n" ::: "memory");
}

// ---------------- Kernel 1: h-projections ----------------
// z=0: g_hxbT = x@Wx + b1 ; z=1: g_hyT = y@Wy
// Tile 32n x 64h, 128 threads, per-thread 4n x 4h (16 indep FFMA per k ->
// LDS/FFMA = 0.16, 16-deep ILP so ~2 blocks/SM self-sustains issue).
// A: coalesced LDG.128 + one-time transpose; W: 32k-chunk smem fills.
// Grid (32, 4, 2) = 256 blocks.
__global__ __launch_bounds__(128) void gemm_h(const float* __restrict__ X,
                                              const float* __restrict__ Y,
                                              const float* __restrict__ W1,
                                              const float* __restrict__ b1) {
    const int z = blockIdx.z;
    const float* A = (z == 0) ? X : Y;
    const float* W = W1 + z * XD * HID;
    float* outT    = (z == 0) ? g_hxbT : g_hyT;

    __shared__ float s_aT[XD][36];   // [k][n], 32 n used, pitch 36 (16B-aligned rows)
    __shared__ float s_w[32][64];    // [k-chunk][h]

    const int tid = threadIdx.x;
    const int gn0 = blockIdx.x * 32;
    const int gh0 = blockIdx.y * 64;

    // Coalesced A load (32 rows x 32 float4) + transpose into s_aT
    #pragma unroll
    for (int r = 0; r < 8; r++) {
        int idx = tid + r * 128;
        int k4 = idx & 31, n_l = idx >> 5;
        float4 v = *(const float4*)(A + (gn0 + n_l) * XD + 4 * k4);
        s_aT[4 * k4 + 0][n_l] = v.x;
        s_aT[4 * k4 + 1][n_l] = v.y;
        s_aT[4 * k4 + 2][n_l] = v.z;
        s_aT[4 * k4 + 3][n_l] = v.w;
    }

    const int tx = tid & 7;         // 8 n-threads, 4 n each
    const int ty = tid >> 3;        // 16 h-threads, 4 h each

    float acc[4][4];                // [hh][nn]
    #pragma unroll
    for (int a = 0; a < 4; a++)
        #pragma unroll
        for (int b = 0; b < 4; b++) acc[a][b] = 0.0f;

    for (int kc = 0; kc < XD; kc += 32) {
        if (kc) __syncthreads();
        // fill s_w: 32k x 64h = 512 float4 (coalesced LDG, conflict-free STS)
        #pragma unroll
        for (int r = 0; r < 4; r++) {
            int idx = tid + r * 128;
            int h4 = idx & 15, k_l = idx >> 4;
            *(float4*)&s_w[k_l][4 * h4] =
                *(const float4*)(W + (kc + k_l) * HID + gh0 + 4 * h4);
        }
        __syncthreads();
        #pragma unroll 8
        for (int k = 0; k < 32; k++) {
            float4 a4 = *(const float4*)&s_aT[kc + k][4 * tx];
            float4 w4 = *(const float4*)&s_w[k][4 * ty];
            float av[4] = {a4.x, a4.y, a4.z, a4.w};
            float wv[4] = {w4.x, w4.y, w4.z, w4.w};
            #pragma unroll
            for (int hh = 0; hh < 4; hh++)
                #pragma unroll
                for (int nn = 0; nn < 4; nn++)
                    acc[hh][nn] = fmaf(wv[hh], av[nn], acc[hh][nn]);
        }
    }

    // write pair-interleaved transposed output (+b1 for z==0)
    #pragma unroll
    for (int hh = 0; hh < 4; hh += 2) {
        int h = gh0 + 4 * ty + hh;              // even
        float bb0 = 0.0f, bb1 = 0.0f;
        if (z == 0) { bb0 = b1[h]; bb1 = b1[h + 1]; }
        #pragma unroll
        for (int nn = 0; nn < 4; nn++) {
            int n = gn0 + 4 * tx + nn;
            *(float2*)&outT[((h >> 1) * NN + n) * 2] =
                make_float2(acc[hh][nn] + bb0, acc[hh + 1][nn] + bb1);
        }
    }
}

// ---------------- Kernel 2: c_i, d_j rank-1 terms (unchanged) -------------
__global__ __launch_bounds__(256) void cd_kernel(const float* __restrict__ W2) {
    __shared__ float sc[256], sd[256];
    const int tid = threadIdx.x;
    const int i = blockIdx.x * 128 + (tid & 127);
    const int half = tid >> 7;
    const float2* hy = (const float2*)g_hyT;
    const float2* hx = (const float2*)g_hxbT;
    const float2* w2 = (const float2*)W2;
    float c = 0.0f, d = 0.0f;
    const int hp0 = half * 64;
    #pragma unroll 8
    for (int hp = hp0; hp < hp0 + 64; hp++) {
        float2 w = w2[hp];
        float2 a = hy[hp * NN + i];
        float2 b = hx[hp * NN + i];
        c = fmaf(a.x, w.x, fmaf(a.y, w.y, c));
        d = fmaf(b.x, w.x, fmaf(b.y, w.y, d));
    }
    sc[tid] = c; sd[tid] = d;
    __syncthreads();
    if (tid < 128) {
        g_c[i] = sc[tid] + sc[tid + 128];
        g_d[i] = sd[tid] + sd[tid + 128];
    }
}

// ---------------- Kernel 3: N^2 pair kernel + fused final reduction -------
// logit[i,j] = 0.5*(sum_h |hy[i,h]+hxb[j,h]|*w2[h] + c_i + d_j) + b2
// lse_i = log(1024 + sum_j e^logit)
// R11 config (best measured): 16i x 64j, 128 thr (4 warps x 4 i; lane ->
// j, j+32), scalar fadd2+FFMA(|z|), cp.async double-buffered, grid 1024.
__global__ __launch_bounds__(128, 8) void pair_kernel(const float* __restrict__ W2,
                                                      const float* __restrict__ b2,
                                                      float* __restrict__ out) {
    __shared__ float s_a[2][16][36];   // [buf][i][h-chunk 32]
    __shared__ float s_b[2][64][36];   // [buf][j][h-chunk 32]
    __shared__ float s_w[HID];
    __shared__ bool  s_last;
    __shared__ float s_red[8];

    const int tid  = threadIdx.x;
    const int lane = tid & 31, w = tid >> 5;   // 4 warps; warp -> 4 i rows
    const int i0 = blockIdx.y * 16;
    const int j0 = blockIdx.x * 64;
    const u64* hyp = (const u64*)g_hyT;
    const u64* hxp = (const u64*)g_hxbT;

    // per-thread fill coordinates (fixed across chunks)
    const int a_i = tid & 15, a_hp = tid >> 4;     // r=0: hp 0..7; r=1: +8
    const int b_j = tid & 63, b_hp = tid >> 6;     // r: hp = b_hp + 2r

    uint32_t sa_base = (uint32_t)__cvta_generic_to_shared(&s_a[0][0][0]);
    uint32_t sb_base = (uint32_t)__cvta_generic_to_shared(&s_b[0][0][0]);
    const uint32_t SA_BUF = 16 * 36 * 4;   // bytes per s_a buffer
    const uint32_t SB_BUF = 64 * 36 * 4;

    s_w[tid]       = W2[tid];
    s_w[tid + 128] = W2[tid + 128];

    float acc[4][2];
    #pragma unroll
    for (int a = 0; a < 4; a++) { acc[a][0] = 0.0f; acc[a][1] = 0.0f; }

    // ---- async fill of chunk `ch` into buffer `b` ----
    auto fill = [&](int ch, int b) {
        const int hp0 = ch * 16;
        uint32_t sa = sa_base + b * SA_BUF;
        uint32_t sb = sb_base + b * SB_BUF;
        #pragma unroll
        for (int r = 0; r < 2; r++) {
            int hp_l = a_hp + r * 8;
            cpa8(sa + (a_i * 36 + 2 * hp_l) * 4,
                 &hyp[(hp0 + hp_l) * NN + i0 + a_i]);
        }
        #pragma unroll
        for (int r = 0; r < 8; r++) {
            int hp_l = b_hp + r * 2;
            cpa8(sb + (b_j * 36 + 2 * hp_l) * 4,
                 &hxp[(hp0 + hp_l) * NN + j0 + b_j]);
        }
        cpa_commit();
    };

    fill(0, 0);
    cpa_wait0();
    __syncthreads();                           // also covers s_w

    int p = 0;
    for (int ch = 0; ch < 8; ch++) {           // 32 h (16 hp) per chunk
        if (ch < 7) fill(ch + 1, p ^ 1);

        #pragma unroll
        for (int st = 0; st < 8; st++) {       // 4 h per step
            float4 wv = *(const float4*)&s_w[ch * 32 + st * 4];
            float4 b0 = *(const float4*)&s_b[p][lane][st * 4];
            float4 b1 = *(const float4*)&s_b[p][lane + 32][st * 4];
            #pragma unroll
            for (int ii = 0; ii < 4; ii++) {
                float4 av = *(const float4*)&s_a[p][w * 4 + ii][st * 4];
                float z0, z1;
                fadd2(z0, z1, av.x, av.y, b0.x, b0.y);
                acc[ii][0] = fmaf(fabsf(z0), wv.x, acc[ii][0]);
                acc[ii][0] = fmaf(fabsf(z1), wv.y, acc[ii][0]);
                fadd2(z0, z1, av.z, av.w, b0.z, b0.w);
                acc[ii][0] = fmaf(fabsf(z0), wv.z, acc[ii][0]);
                acc[ii][0] = fmaf(fabsf(z1), wv.w, acc[ii][0]);
                fadd2(z0, z1, av.x, av.y, b1.x, b1.y);
                acc[ii][1] = fmaf(fabsf(z0), wv.x, acc[ii][1]);
                acc[ii][1] = fmaf(fabsf(z1), wv.y, acc[ii][1]);
                fadd2(z0, z1, av.z, av.w, b1.z, b1.w);
                acc[ii][1] = fmaf(fabsf(z0), wv.z, acc[ii][1]);
                acc[ii][1] = fmaf(fabsf(z1), wv.w, acc[ii][1]);
            }
        }

        if (ch < 7) {
            cpa_wait0();
            __syncthreads();
            p ^= 1;
        }
    }

    // ---- epilogue ----
    const float b2v = b2[0];
    const int gj0 = j0 + lane, gj1 = j0 + lane + 32;
    const float d0 = g_d[gj0], d1 = g_d[gj1];
    #pragma unroll
    for (int ii = 0; ii < 4; ii++) {
        const int gi = i0 + w * 4 + ii;
        const float ci = g_c[gi];
        float l0 = 0.5f * (acc[ii][0] + ci + d0) + b2v;
        float l1 = 0.5f * (acc[ii][1] + ci + d1) + b2v;
        float e = __expf(l0) + __expf(l1);
        if (gi == gj0) g_diag[gi] = fmaxf(l0, 0.0f) + log1pf(__expf(-fabsf(l0)));
        if (gi == gj1) g_diag[gi] = fmaxf(l1, 0.0f) + log1pf(__expf(-fabsf(l1)));
        e += __shfl_xor_sync(0xFFFFFFFFu, e, 16);
        e += __shfl_xor_sync(0xFFFFFFFFu, e, 8);
        e += __shfl_xor_sync(0xFFFFFFFFu, e, 4);
        e += __shfl_xor_sync(0xFFFFFFFFu, e, 2);
        e += __shfl_xor_sync(0xFFFFFFFFu, e, 1);
        if (lane == 0) g_part[gi * 16 + blockIdx.x] = e;
    }

    // ---- last block does the final reduction ----
    __threadfence();
    __syncthreads();
    if (tid == 0) {
        int old = atomicAdd(&g_ctr, 1);
        s_last = (old == 16 * 64 - 1);
    }
    __syncthreads();
    if (!s_last) return;
    __threadfence();

    float sumT0 = 0.0f, sumL = 0.0f;
    #pragma unroll
    for (int r = 0; r < 8; r++) {
        int i = tid * 8 + r;
        const float4* pp = (const float4*)&g_part[i * 16];
        float4 a = pp[0], b = pp[1], c = pp[2], d = pp[3];
        float s = ((a.x + a.y) + (a.z + a.w)) + ((b.x + b.y) + (b.z + b.w)) +
                  ((c.x + c.y) + (c.z + c.w)) + ((d.x + d.y) + (d.z + d.w));
        sumL  += __logf(1024.0f + s);
        sumT0 += g_diag[i];
    }
    #pragma unroll
    for (int dlt = 16; dlt >= 1; dlt >>= 1) {
        sumT0 += __shfl_xor_sync(0xFFFFFFFFu, sumT0, dlt);
        sumL  += __shfl_xor_sync(0xFFFFFFFFu, sumL,  dlt);
    }
    if (lane == 0) { s_red[w] = sumT0; s_red[4 + w] = sumL; }
    __syncthreads();
    if (tid == 0) {
        float t0 = (s_red[0] + s_red[1]) + (s_red[2] + s_red[3]);
        float l  = (s_red[4] + s_red[5]) + (s_red[6] + s_red[7]);
        const float invn = 1.0f / 1024.0f;
        out[0] = t0 * invn - (l * invn - logf(1024.0f));
        g_ctr = 0;
    }
}

// ---------------- launch ----------------
extern "C" void kernel_launch(void* const* d_in, const int* in_sizes, int n_in,
                              void* d_out, int out_size) {
    (void)in_sizes; (void)n_in; (void)out_size;
    const float* X  = (const float*)d_in[0];
    const float* Y  = (const float*)d_in[1];
    const float* W1 = (const float*)d_in[2];
    const float* b1 = (const float*)d_in[3];
    const float* W2 = (const float*)d_in[4];
    const float* b2 = (const float*)d_in[5];

    gemm_h   <<<dim3(32, 4, 2), 128>>>(X, Y, W1, b1);
    cd_kernel<<<8, 256>>>(W2);
    pair_kernel<<<dim3(16, 64), 128>>>(W2, b2, (float*)d_out);
}

// round 16
// speedup vs baseline: 1.5310x; 1.2530x over previous
#include <cuda_runtime.h>
#include <cstdint>

#define NN   1024
#define XD   128
#define HID  256
#define HP   128   // h-pairs

typedef unsigned long long u64;

// ---------------- scratch (device globals; no allocations) ----------------
__device__ float g_hxbT[HP * NN * 2];   // hx + b1, transposed, pair-interleaved [hp][n]{2}
__device__ float g_hyT [HP * NN * 2];   // hy, same layout
__device__ float g_cdp[8 * NN];         // partial c/d dots: [z*4 + h-block][n]
__device__ float g_part[NN * 16];       // per (i, j-block) sum of exp(logit)
__device__ float g_diag[NN];            // T0_i = softplus(logit_ii)
__device__ int   g_ctr;

// ---------------- helpers ----------------
__device__ __forceinline__ void fadd2(float& r0, float& r1,
                                      float a0, float a1, float b0, float b1) {
    asm("{\n\t"
        ".reg .b64 ra, rb, rc;\n\t"
        "mov.b64 ra, {%2, %3};\n\t"
        "mov.b64 rb, {%4, %5};\n\t"
        "add.rn.f32x2 rc, ra, rb;\n\t"
        "mov.b64 {%0, %1}, rc;\n\t"
        "}" : "=f"(r0), "=f"(r1) : "f"(a0), "f"(a1), "f"(b0), "f"(b1));
}

__device__ __forceinline__ void cpa8(uint32_t dst, const void* src) {
    asm volatile("cp.async.ca.shared.global [%0], [%1], 8;\n"
                 :: "r"(dst), "l"(src));
}
__device__ __forceinline__ void cpa16(uint32_t dst, const void* src) {
    asm volatile("cp.async.cg.shared.global [%0], [%1], 16;\n"
                 :: "r"(dst), "l"(src));
}
__device__ __forceinline__ void cpa_commit() {
    asm volatile("cp.async.commit_group;\n" ::: "memory");
}
__device__ __forceinline__ void cpa_wait0() {
    asm volatile("cp.async.wait_group 0;\n" ::: "memory");
}

// ---------------- Kernel 1: h-projections + fused partial c/d dots --------
// z=0: g_hxbT = x@Wx + b1  (and d-partials) ; z=1: g_hyT = y@Wy (c-partials)
// Tile 32n x 64h, 128 threads (4n x 4h per thread). W chunks (32k x 64h)
// double-buffered via cp.async.cg so fill latency overlaps compute.
// Epilogue also computes partial_cd[n] = sum_{h in block} out*w2[h] ->
// g_cdp[z*4 + blockIdx.y][n], replacing the separate cd kernel.
__global__ __launch_bounds__(128) void gemm_h(const float* __restrict__ X,
                                              const float* __restrict__ Y,
                                              const float* __restrict__ W1,
                                              const float* __restrict__ b1,
                                              const float* __restrict__ W2) {
    const int z = blockIdx.z;
    const float* A = (z == 0) ? X : Y;
    const float* W = W1 + z * XD * HID;
    float* outT    = (z == 0) ? g_hxbT : g_hyT;

    __shared__ float s_aT[XD][36];      // [k][n], 32 n used, pitch 36 (16B rows)
    __shared__ float s_wb[2][32][64];   // double-buffered W chunk
    __shared__ float s_p[16][32];       // partial-dot reduction [ty][n]

    const int tid = threadIdx.x;
    const int gn0 = blockIdx.x * 32;
    const int gh0 = blockIdx.y * 64;

    uint32_t swb_base = (uint32_t)__cvta_generic_to_shared(&s_wb[0][0][0]);
    const uint32_t WB_BUF = 32 * 64 * 4;   // 8 KB

    // async W-fill of k-chunk `c` (32 k) into buffer `b`
    auto fillW = [&](int c, int b) {
        const int kc = c * 32;
        #pragma unroll
        for (int r = 0; r < 4; r++) {
            int idx = tid + r * 128;
            int h4 = idx & 15, k_l = idx >> 4;
            cpa16(swb_base + b * WB_BUF + (k_l * 64 + 4 * h4) * 4,
                  W + (kc + k_l) * HID + gh0 + 4 * h4);
        }
        cpa_commit();
    };

    fillW(0, 0);

    // A load (coalesced LDG.128) + transpose into s_aT — overlaps W fill
    #pragma unroll
    for (int r = 0; r < 8; r++) {
        int idx = tid + r * 128;
        int k4 = idx & 31, n_l = idx >> 5;
        float4 v = *(const float4*)(A + (gn0 + n_l) * XD + 4 * k4);
        s_aT[4 * k4 + 0][n_l] = v.x;
        s_aT[4 * k4 + 1][n_l] = v.y;
        s_aT[4 * k4 + 2][n_l] = v.z;
        s_aT[4 * k4 + 3][n_l] = v.w;
    }

    const int tx = tid & 7;         // 8 n-threads, 4 n each
    const int ty = tid >> 3;        // 16 h-threads, 4 h each

    float acc[4][4];                // [hh][nn]
    #pragma unroll
    for (int a = 0; a < 4; a++)
        #pragma unroll
        for (int b = 0; b < 4; b++) acc[a][b] = 0.0f;

    cpa_wait0();
    __syncthreads();                // W chunk0 + A transpose both ready

    int p = 0;
    for (int c = 0; c < 4; c++) {   // 4 k-chunks of 32
        if (c < 3) fillW(c + 1, p ^ 1);
        const int kc = c * 32;
        #pragma unroll 8
        for (int k = 0; k < 32; k++) {
            float4 a4 = *(const float4*)&s_aT[kc + k][4 * tx];
            float4 w4 = *(const float4*)&s_wb[p][k][4 * ty];
            float av[4] = {a4.x, a4.y, a4.z, a4.w};
            float wv[4] = {w4.x, w4.y, w4.z, w4.w};
            #pragma unroll
            for (int hh = 0; hh < 4; hh++)
                #pragma unroll
                for (int nn = 0; nn < 4; nn++)
                    acc[hh][nn] = fmaf(wv[hh], av[nn], acc[hh][nn]);
        }
        if (c < 3) {
            cpa_wait0();
            __syncthreads();
            p ^= 1;
        }
    }

    // epilogue: add bias, write pair-interleaved output, partial c/d dots
    const int hbase = gh0 + 4 * ty;
    float w2h[4], vout[4][4];
    #pragma unroll
    for (int hh = 0; hh < 4; hh++) {
        float bb = (z == 0) ? b1[hbase + hh] : 0.0f;
        w2h[hh] = W2[hbase + hh];
        #pragma unroll
        for (int nn = 0; nn < 4; nn++) vout[hh][nn] = acc[hh][nn] + bb;
    }
    #pragma unroll
    for (int hh = 0; hh < 4; hh += 2) {
        int h = hbase + hh;                     // even
        #pragma unroll
        for (int nn = 0; nn < 4; nn++) {
            int n = gn0 + 4 * tx + nn;
            *(float2*)&outT[((h >> 1) * NN + n) * 2] =
                make_float2(vout[hh][nn], vout[hh + 1][nn]);
        }
    }
    #pragma unroll
    for (int nn = 0; nn < 4; nn++) {
        float pc = fmaf(vout[0][nn], w2h[0], fmaf(vout[1][nn], w2h[1],
                   fmaf(vout[2][nn], w2h[2], vout[3][nn] * w2h[3])));
        s_p[ty][4 * tx + nn] = pc;
    }
    __syncthreads();
    if (tid < 32) {
        float s = 0.0f;
        #pragma unroll
        for (int q = 0; q < 16; q++) s += s_p[q][tid];
        g_cdp[(z * 4 + blockIdx.y) * NN + gn0 + tid] = s;
    }
}

// ---------------- Kernel 2: N^2 pair kernel + fused final reduction -------
// logit[i,j] = 0.5*(sum_h |hy[i,h]+hxb[j,h]|*w2[h] + c_i + d_j) + b2
// lse_i = log(1024 + sum_j e^logit)
// R11 config (best measured): 16i x 64j, 128 thr, scalar fadd2+FFMA(|z|),
// cp.async double-buffered, grid 1024. c_i/d_j summed from gemm partials.
__global__ __launch_bounds__(128, 8) void pair_kernel(const float* __restrict__ W2,
                                                      const float* __restrict__ b2,
                                                      float* __restrict__ out) {
    __shared__ float s_a[2][16][36];   // [buf][i][h-chunk 32]
    __shared__ float s_b[2][64][36];   // [buf][j][h-chunk 32]
    __shared__ float s_w[HID];
    __shared__ bool  s_last;
    __shared__ float s_red[8];

    const int tid  = threadIdx.x;
    const int lane = tid & 31, w = tid >> 5;   // 4 warps; warp -> 4 i rows
    const int i0 = blockIdx.y * 16;
    const int j0 = blockIdx.x * 64;
    const u64* hyp = (const u64*)g_hyT;
    const u64* hxp = (const u64*)g_hxbT;

    const int a_i = tid & 15, a_hp = tid >> 4;     // r=0: hp 0..7; r=1: +8
    const int b_j = tid & 63, b_hp = tid >> 6;     // r: hp = b_hp + 2r

    uint32_t sa_base = (uint32_t)__cvta_generic_to_shared(&s_a[0][0][0]);
    uint32_t sb_base = (uint32_t)__cvta_generic_to_shared(&s_b[0][0][0]);
    const uint32_t SA_BUF = 16 * 36 * 4;
    const uint32_t SB_BUF = 64 * 36 * 4;

    s_w[tid]       = W2[tid];
    s_w[tid + 128] = W2[tid + 128];

    float acc[4][2];
    #pragma unroll
    for (int a = 0; a < 4; a++) { acc[a][0] = 0.0f; acc[a][1] = 0.0f; }

    auto fill = [&](int ch, int b) {
        const int hp0 = ch * 16;
        uint32_t sa = sa_base + b * SA_BUF;
        uint32_t sb = sb_base + b * SB_BUF;
        #pragma unroll
        for (int r = 0; r < 2; r++) {
            int hp_l = a_hp + r * 8;
            cpa8(sa + (a_i * 36 + 2 * hp_l) * 4,
                 &hyp[(hp0 + hp_l) * NN + i0 + a_i]);
        }
        #pragma unroll
        for (int r = 0; r < 8; r++) {
            int hp_l = b_hp + r * 2;
            cpa8(sb + (b_j * 36 + 2 * hp_l) * 4,
                 &hxp[(hp0 + hp_l) * NN + j0 + b_j]);
        }
        cpa_commit();
    };

    fill(0, 0);
    cpa_wait0();
    __syncthreads();                           // also covers s_w

    int p = 0;
    for (int ch = 0; ch < 8; ch++) {           // 32 h (16 hp) per chunk
        if (ch < 7) fill(ch + 1, p ^ 1);

        #pragma unroll
        for (int st = 0; st < 8; st++) {       // 4 h per step
            float4 wv = *(const float4*)&s_w[ch * 32 + st * 4];
            float4 b0 = *(const float4*)&s_b[p][lane][st * 4];
            float4 b1 = *(const float4*)&s_b[p][lane + 32][st * 4];
            #pragma unroll
            for (int ii = 0; ii < 4; ii++) {
                float4 av = *(const float4*)&s_a[p][w * 4 + ii][st * 4];
                float z0, z1;
                fadd2(z0, z1, av.x, av.y, b0.x, b0.y);
                acc[ii][0] = fmaf(fabsf(z0), wv.x, acc[ii][0]);
                acc[ii][0] = fmaf(fabsf(z1), wv.y, acc[ii][0]);
                fadd2(z0, z1, av.z, av.w, b0.z, b0.w);
                acc[ii][0] = fmaf(fabsf(z0), wv.z, acc[ii][0]);
                acc[ii][0] = fmaf(fabsf(z1), wv.w, acc[ii][0]);
                fadd2(z0, z1, av.x, av.y, b1.x, b1.y);
                acc[ii][1] = fmaf(fabsf(z0), wv.x, acc[ii][1]);
                acc[ii][1] = fmaf(fabsf(z1), wv.y, acc[ii][1]);
                fadd2(z0, z1, av.z, av.w, b1.z, b1.w);
                acc[ii][1] = fmaf(fabsf(z0), wv.z, acc[ii][1]);
                acc[ii][1] = fmaf(fabsf(z1), wv.w, acc[ii][1]);
            }
        }

        if (ch < 7) {
            cpa_wait0();
            __syncthreads();
            p ^= 1;
        }
    }

    // ---- epilogue: sum c/d from gemm partials, then exp-sum ----
    const float b2v = b2[0];
    const int gj0 = j0 + lane, gj1 = j0 + lane + 32;
    const float d0 = (g_cdp[0 * NN + gj0] + g_cdp[1 * NN + gj0]) +
                     (g_cdp[2 * NN + gj0] + g_cdp[3 * NN + gj0]);
    const float d1 = (g_cdp[0 * NN + gj1] + g_cdp[1 * NN + gj1]) +
                     (g_cdp[2 * NN + gj1] + g_cdp[3 * NN + gj1]);
    #pragma unroll
    for (int ii = 0; ii < 4; ii++) {
        const int gi = i0 + w * 4 + ii;
        const float ci = (g_cdp[4 * NN + gi] + g_cdp[5 * NN + gi]) +
                         (g_cdp[6 * NN + gi] + g_cdp[7 * NN + gi]);
        float l0 = 0.5f * (acc[ii][0] + ci + d0) + b2v;
        float l1 = 0.5f * (acc[ii][1] + ci + d1) + b2v;
        float e = __expf(l0) + __expf(l1);
        if (gi == gj0) g_diag[gi] = fmaxf(l0, 0.0f) + log1pf(__expf(-fabsf(l0)));
        if (gi == gj1) g_diag[gi] = fmaxf(l1, 0.0f) + log1pf(__expf(-fabsf(l1)));
        e += __shfl_xor_sync(0xFFFFFFFFu, e, 16);
        e += __shfl_xor_sync(0xFFFFFFFFu, e, 8);
        e += __shfl_xor_sync(0xFFFFFFFFu, e, 4);
        e += __shfl_xor_sync(0xFFFFFFFFu, e, 2);
        e += __shfl_xor_sync(0xFFFFFFFFu, e, 1);
        if (lane == 0) g_part[gi * 16 + blockIdx.x] = e;
    }

    // ---- last block does the final reduction ----
    __threadfence();
    __syncthreads();
    if (tid == 0) {
        int old = atomicAdd(&g_ctr, 1);
        s_last = (old == 16 * 64 - 1);
    }
    __syncthreads();
    if (!s_last) return;
    __threadfence();

    float sumT0 = 0.0f, sumL = 0.0f;
    #pragma unroll
    for (int r = 0; r < 8; r++) {
        int i = tid * 8 + r;
        const float4* pp = (const float4*)&g_part[i * 16];
        float4 a = pp[0], b = pp[1], c = pp[2], d = pp[3];
        float s = ((a.x + a.y) + (a.z + a.w)) + ((b.x + b.y) + (b.z + b.w)) +
                  ((c.x + c.y) + (c.z + c.w)) + ((d.x + d.y) + (d.z + d.w));
        sumL  += __logf(1024.0f + s);
        sumT0 += g_diag[i];
    }
    #pragma unroll
    for (int dlt = 16; dlt >= 1; dlt >>= 1) {
        sumT0 += __shfl_xor_sync(0xFFFFFFFFu, sumT0, dlt);
        sumL  += __shfl_xor_sync(0xFFFFFFFFu, sumL,  dlt);
    }
    if (lane == 0) { s_red[w] = sumT0; s_red[4 + w] = sumL; }
    __syncthreads();
    if (tid == 0) {
        float t0 = (s_red[0] + s_red[1]) + (s_red[2] + s_red[3]);
        float l  = (s_red[4] + s_red[5]) + (s_red[6] + s_red[7]);
        const float invn = 1.0f / 1024.0f;
        out[0] = t0 * invn - (l * invn - logf(1024.0f));
        g_ctr = 0;
    }
}

// ---------------- launch ----------------
extern "C" void kernel_launch(void* const* d_in, const int* in_sizes, int n_in,
                              void* d_out, int out_size) {
    (void)in_sizes; (void)n_in; (void)out_size;
    const float* X  = (const float*)d_in[0];
    const float* Y  = (const float*)d_in[1];
    const float* W1 = (const float*)d_in[2];
    const float* b1 = (const float*)d_in[3];
    const float* W2 = (const float*)d_in[4];
    const float* b2 = (const float*)d_in[5];

    gemm_h   <<<dim3(32, 4, 2), 128>>>(X, Y, W1, b1, W2);
    pair_kernel<<<dim3(16, 64), 128>>>(W2, b2, (float*)d_out);
}

// round 17
// speedup vs baseline: 1.5383x; 1.0047x over previous
#include <cuda_runtime.h>
#include <cstdint>

#define NN   1024
#define XD   128
#define HID  256
#define HP   128   // h-pairs

typedef unsigned long long u64;

// ---------------- scratch (device globals; no allocations) ----------------
__device__ float g_hxbT[HP * NN * 2];   // hx + b1, transposed, pair-interleaved [hp][n]{2}
__device__ float g_hyT [HP * NN * 2];   // hy, same layout
__device__ float g_cdp[8 * NN];         // partial c/d dots: [z*4 + h-block][n]
__device__ float g_part[NN * 16];       // per (i, j-block) sum of exp(logit)
__device__ float g_diag[NN];            // T0_i = softplus(logit_ii)
__device__ int   g_ctr;

// ---------------- helpers ----------------
__device__ __forceinline__ void fadd2(float& r0, float& r1,
                                      float a0, float a1, float b0, float b1) {
    asm("{\n\t"
        ".reg .b64 ra, rb, rc;\n\t"
        "mov.b64 ra, {%2, %3};\n\t"
        "mov.b64 rb, {%4, %5};\n\t"
        "add.rn.f32x2 rc, ra, rb;\n\t"
        "mov.b64 {%0, %1}, rc;\n\t"
        "}" : "=f"(r0), "=f"(r1) : "f"(a0), "f"(a1), "f"(b0), "f"(b1));
}

__device__ __forceinline__ void cpa8(uint32_t dst, const void* src) {
    asm volatile("cp.async.ca.shared.global [%0], [%1], 8;\n"
                 :: "r"(dst), "l"(src));
}
__device__ __forceinline__ void cpa16(uint32_t dst, const void* src) {
    asm volatile("cp.async.cg.shared.global [%0], [%1], 16;\n"
                 :: "r"(dst), "l"(src));
}
__device__ __forceinline__ void cpa_commit() {
    asm volatile("cp.async.commit_group;\n" ::: "memory");
}
__device__ __forceinline__ void cpa_wait0() {
    asm volatile("cp.async.wait_group 0;\n" ::: "memory");
}

// ---------------- Kernel 1: h-projections + fused partial c/d dots --------
// (unchanged from R16 — cp.async double-buffered W, fused c/d partials)
__global__ __launch_bounds__(128) void gemm_h(const float* __restrict__ X,
                                              const float* __restrict__ Y,
                                              const float* __restrict__ W1,
                                              const float* __restrict__ b1,
                                              const float* __restrict__ W2) {
    const int z = blockIdx.z;
    const float* A = (z == 0) ? X : Y;
    const float* W = W1 + z * XD * HID;
    float* outT    = (z == 0) ? g_hxbT : g_hyT;

    __shared__ float s_aT[XD][36];      // [k][n], 32 n used, pitch 36 (16B rows)
    __shared__ float s_wb[2][32][64];   // double-buffered W chunk
    __shared__ float s_p[16][32];       // partial-dot reduction [ty][n]

    const int tid = threadIdx.x;
    const int gn0 = blockIdx.x * 32;
    const int gh0 = blockIdx.y * 64;

    uint32_t swb_base = (uint32_t)__cvta_generic_to_shared(&s_wb[0][0][0]);
    const uint32_t WB_BUF = 32 * 64 * 4;   // 8 KB

    auto fillW = [&](int c, int b) {
        const int kc = c * 32;
        #pragma unroll
        for (int r = 0; r < 4; r++) {
            int idx = tid + r * 128;
            int h4 = idx & 15, k_l = idx >> 4;
            cpa16(swb_base + b * WB_BUF + (k_l * 64 + 4 * h4) * 4,
                  W + (kc + k_l) * HID + gh0 + 4 * h4);
        }
        cpa_commit();
    };

    fillW(0, 0);

    #pragma unroll
    for (int r = 0; r < 8; r++) {
        int idx = tid + r * 128;
        int k4 = idx & 31, n_l = idx >> 5;
        float4 v = *(const float4*)(A + (gn0 + n_l) * XD + 4 * k4);
        s_aT[4 * k4 + 0][n_l] = v.x;
        s_aT[4 * k4 + 1][n_l] = v.y;
        s_aT[4 * k4 + 2][n_l] = v.z;
        s_aT[4 * k4 + 3][n_l] = v.w;
    }

    const int tx = tid & 7;         // 8 n-threads, 4 n each
    const int ty = tid >> 3;        // 16 h-threads, 4 h each

    float acc[4][4];                // [hh][nn]
    #pragma unroll
    for (int a = 0; a < 4; a++)
        #pragma unroll
        for (int b = 0; b < 4; b++) acc[a][b] = 0.0f;

    cpa_wait0();
    __syncthreads();

    int p = 0;
    for (int c = 0; c < 4; c++) {   // 4 k-chunks of 32
        if (c < 3) fillW(c + 1, p ^ 1);
        const int kc = c * 32;
        #pragma unroll 8
        for (int k = 0; k < 32; k++) {
            float4 a4 = *(const float4*)&s_aT[kc + k][4 * tx];
            float4 w4 = *(const float4*)&s_wb[p][k][4 * ty];
            float av[4] = {a4.x, a4.y, a4.z, a4.w};
            float wv[4] = {w4.x, w4.y, w4.z, w4.w};
            #pragma unroll
            for (int hh = 0; hh < 4; hh++)
                #pragma unroll
                for (int nn = 0; nn < 4; nn++)
                    acc[hh][nn] = fmaf(wv[hh], av[nn], acc[hh][nn]);
        }
        if (c < 3) {
            cpa_wait0();
            __syncthreads();
            p ^= 1;
        }
    }

    const int hbase = gh0 + 4 * ty;
    float w2h[4], vout[4][4];
    #pragma unroll
    for (int hh = 0; hh < 4; hh++) {
        float bb = (z == 0) ? b1[hbase + hh] : 0.0f;
        w2h[hh] = W2[hbase + hh];
        #pragma unroll
        for (int nn = 0; nn < 4; nn++) vout[hh][nn] = acc[hh][nn] + bb;
    }
    #pragma unroll
    for (int hh = 0; hh < 4; hh += 2) {
        int h = hbase + hh;
        #pragma unroll
        for (int nn = 0; nn < 4; nn++) {
            int n = gn0 + 4 * tx + nn;
            *(float2*)&outT[((h >> 1) * NN + n) * 2] =
                make_float2(vout[hh][nn], vout[hh + 1][nn]);
        }
    }
    #pragma unroll
    for (int nn = 0; nn < 4; nn++) {
        float pc = fmaf(vout[0][nn], w2h[0], fmaf(vout[1][nn], w2h[1],
                   fmaf(vout[2][nn], w2h[2], vout[3][nn] * w2h[3])));
        s_p[ty][4 * tx + nn] = pc;
    }
    __syncthreads();
    if (tid < 32) {
        float s = 0.0f;
        #pragma unroll
        for (int q = 0; q < 16; q++) s += s_p[q][tid];
        g_cdp[(z * 4 + blockIdx.y) * NN + gn0 + tid] = s;
    }
}

// ---------------- Kernel 2: N^2 pair kernel + fused final reduction -------
// logit[i,j] = 0.5*(sum_h |hy[i,h]+hxb[j,h]|*w2[h] + c_i + d_j) + b2
// lse_i = log(1024 + sum_j e^logit)
// Tile 32i x 64j, 128 thr (4 warps x 8 i-rows; lane -> j, j+32).
// 8i register blocking cuts LDS/fma 0.27 -> 0.177 (L1 was the 60% ceiling).
// cp.async double-buffered. Grid 512 blocks.
__global__ __launch_bounds__(128, 6) void pair_kernel(const float* __restrict__ W2,
                                                      const float* __restrict__ b2,
                                                      float* __restrict__ out) {
    __shared__ float s_a[2][32][36];   // [buf][i][h-chunk 32]
    __shared__ float s_b[2][64][36];   // [buf][j][h-chunk 32]
    __shared__ float s_w[HID];
    __shared__ bool  s_last;
    __shared__ float s_red[8];

    const int tid  = threadIdx.x;
    const int lane = tid & 31, w = tid >> 5;   // 4 warps; warp -> 8 i rows
    const int i0 = blockIdx.y * 32;
    const int j0 = blockIdx.x * 64;
    const u64* hyp = (const u64*)g_hyT;
    const u64* hxp = (const u64*)g_hxbT;

    // per-thread fill coordinates
    const int a_i = tid & 31, a_hp = tid >> 5;     // r<4: hp = a_hp + 4r
    const int b_j = tid & 63, b_hp = tid >> 6;     // r<8: hp = b_hp + 2r

    uint32_t sa_base = (uint32_t)__cvta_generic_to_shared(&s_a[0][0][0]);
    uint32_t sb_base = (uint32_t)__cvta_generic_to_shared(&s_b[0][0][0]);
    const uint32_t SA_BUF = 32 * 36 * 4;
    const uint32_t SB_BUF = 64 * 36 * 4;

    s_w[tid]       = W2[tid];
    s_w[tid + 128] = W2[tid + 128];

    float acc[8][2];
    #pragma unroll
    for (int a = 0; a < 8; a++) { acc[a][0] = 0.0f; acc[a][1] = 0.0f; }

    auto fill = [&](int ch, int b) {
        const int hp0 = ch * 16;
        uint32_t sa = sa_base + b * SA_BUF;
        uint32_t sb = sb_base + b * SB_BUF;
        #pragma unroll
        for (int r = 0; r < 4; r++) {
            int hp_l = a_hp + r * 4;
            cpa8(sa + (a_i * 36 + 2 * hp_l) * 4,
                 &hyp[(hp0 + hp_l) * NN + i0 + a_i]);
        }
        #pragma unroll
        for (int r = 0; r < 8; r++) {
            int hp_l = b_hp + r * 2;
            cpa8(sb + (b_j * 36 + 2 * hp_l) * 4,
                 &hxp[(hp0 + hp_l) * NN + j0 + b_j]);
        }
        cpa_commit();
    };

    fill(0, 0);
    cpa_wait0();
    __syncthreads();                           // also covers s_w

    int p = 0;
    for (int ch = 0; ch < 8; ch++) {           // 32 h (16 hp) per chunk
        if (ch < 7) fill(ch + 1, p ^ 1);

        #pragma unroll
        for (int st = 0; st < 8; st++) {       // 4 h per step
            float4 wv = *(const float4*)&s_w[ch * 32 + st * 4];
            float4 b0 = *(const float4*)&s_b[p][lane][st * 4];
            float4 b1 = *(const float4*)&s_b[p][lane + 32][st * 4];
            #pragma unroll
            for (int ii = 0; ii < 8; ii++) {
                float4 av = *(const float4*)&s_a[p][w * 8 + ii][st * 4];
                float z0, z1;
                fadd2(z0, z1, av.x, av.y, b0.x, b0.y);
                acc[ii][0] = fmaf(fabsf(z0), wv.x, acc[ii][0]);
                acc[ii][0] = fmaf(fabsf(z1), wv.y, acc[ii][0]);
                fadd2(z0, z1, av.z, av.w, b0.z, b0.w);
                acc[ii][0] = fmaf(fabsf(z0), wv.z, acc[ii][0]);
                acc[ii][0] = fmaf(fabsf(z1), wv.w, acc[ii][0]);
                fadd2(z0, z1, av.x, av.y, b1.x, b1.y);
                acc[ii][1] = fmaf(fabsf(z0), wv.x, acc[ii][1]);
                acc[ii][1] = fmaf(fabsf(z1), wv.y, acc[ii][1]);
                fadd2(z0, z1, av.z, av.w, b1.z, b1.w);
                acc[ii][1] = fmaf(fabsf(z0), wv.z, acc[ii][1]);
                acc[ii][1] = fmaf(fabsf(z1), wv.w, acc[ii][1]);
            }
        }

        if (ch < 7) {
            cpa_wait0();
            __syncthreads();
            p ^= 1;
        }
    }

    // ---- epilogue: sum c/d from gemm partials, then exp-sum ----
    const float b2v = b2[0];
    const int gj0 = j0 + lane, gj1 = j0 + lane + 32;
    const float d0 = (g_cdp[0 * NN + gj0] + g_cdp[1 * NN + gj0]) +
                     (g_cdp[2 * NN + gj0] + g_cdp[3 * NN + gj0]);
    const float d1 = (g_cdp[0 * NN + gj1] + g_cdp[1 * NN + gj1]) +
                     (g_cdp[2 * NN + gj1] + g_cdp[3 * NN + gj1]);
    #pragma unroll
    for (int ii = 0; ii < 8; ii++) {
        const int gi = i0 + w * 8 + ii;
        const float ci = (g_cdp[4 * NN + gi] + g_cdp[5 * NN + gi]) +
                         (g_cdp[6 * NN + gi] + g_cdp[7 * NN + gi]);
        float l0 = 0.5f * (acc[ii][0] + ci + d0) + b2v;
        float l1 = 0.5f * (acc[ii][1] + ci + d1) + b2v;
        float e = __expf(l0) + __expf(l1);
        if (gi == gj0) g_diag[gi] = fmaxf(l0, 0.0f) + log1pf(__expf(-fabsf(l0)));
        if (gi == gj1) g_diag[gi] = fmaxf(l1, 0.0f) + log1pf(__expf(-fabsf(l1)));
        e += __shfl_xor_sync(0xFFFFFFFFu, e, 16);
        e += __shfl_xor_sync(0xFFFFFFFFu, e, 8);
        e += __shfl_xor_sync(0xFFFFFFFFu, e, 4);
        e += __shfl_xor_sync(0xFFFFFFFFu, e, 2);
        e += __shfl_xor_sync(0xFFFFFFFFu, e, 1);
        if (lane == 0) g_part[gi * 16 + blockIdx.x] = e;
    }

    // ---- last block does the final reduction ----
    __threadfence();
    __syncthreads();
    if (tid == 0) {
        int old = atomicAdd(&g_ctr, 1);
        s_last = (old == 16 * 32 - 1);
    }
    __syncthreads();
    if (!s_last) return;
    __threadfence();

    float sumT0 = 0.0f, sumL = 0.0f;
    #pragma unroll
    for (int r = 0; r < 8; r++) {
        int i = tid * 8 + r;
        const float4* pp = (const float4*)&g_part[i * 16];
        float4 a = pp[0], b = pp[1], c = pp[2], d = pp[3];
        float s = ((a.x + a.y) + (a.z + a.w)) + ((b.x + b.y) + (b.z + b.w)) +
                  ((c.x + c.y) + (c.z + c.w)) + ((d.x + d.y) + (d.z + d.w));
        sumL  += __logf(1024.0f + s);
        sumT0 += g_diag[i];
    }
    #pragma unroll
    for (int dlt = 16; dlt >= 1; dlt >>= 1) {
        sumT0 += __shfl_xor_sync(0xFFFFFFFFu, sumT0, dlt);
        sumL  += __shfl_xor_sync(0xFFFFFFFFu, sumL,  dlt);
    }
    if (lane == 0) { s_red[w] = sumT0; s_red[4 + w] = sumL; }
    __syncthreads();
    if (tid == 0) {
        float t0 = (s_red[0] + s_red[1]) + (s_red[2] + s_red[3]);
        float l  = (s_red[4] + s_red[5]) + (s_red[6] + s_red[7]);
        const float invn = 1.0f / 1024.0f;
        out[0] = t0 * invn - (l * invn - logf(1024.0f));
        g_ctr = 0;
    }
}

// ---------------- launch ----------------
extern "C" void kernel_launch(void* const* d_in, const int* in_sizes, int n_in,
                              void* d_out, int out_size) {
    (void)in_sizes; (void)n_in; (void)out_size;
    const float* X  = (const float*)d_in[0];
    const float* Y  = (const float*)d_in[1];
    const float* W1 = (const float*)d_in[2];
    const float* b1 = (const float*)d_in[3];
    const float* W2 = (const float*)d_in[4];
    const float* b2 = (const float*)d_in[5];

    gemm_h   <<<dim3(32, 4, 2), 128>>>(X, Y, W1, b1, W2);
    pair_kernel<<<dim3(16, 32), 128>>>(W2, b2, (float*)d_out);
}